// round 9
// baseline (speedup 1.0000x reference)
#include <cuda_runtime.h>
#include <math.h>

#define DDIM 512        // feature dim per row
#define GROUPS 128      // groups per row (one full row per block)
#define KCODES 1024
#define KPAIRS 512
#define NTHREADS 256    // 8 warps
#define NWARPS 8
#define PPCHUNK 64      // k-pairs per warp chunk (8 warps x 64 pairs = 1024 codes)
#define IDXMASK 0x3FFu
#define PACKMASK 0xFFFFFC00u

__device__ float g_partials[512];
__device__ int   g_count = 0;

// ---- f32x2 packed helpers (sm_103a) ----
__device__ __forceinline__ unsigned long long pack2(float lo, float hi) {
    unsigned long long r;
    asm("mov.b64 %0, {%1, %2};" : "=l"(r)
        : "r"(__float_as_uint(lo)), "r"(__float_as_uint(hi)));
    return r;
}
__device__ __forceinline__ void unpack2(unsigned long long v, unsigned& lo, unsigned& hi) {
    asm("mov.b64 {%0, %1}, %2;" : "=r"(lo), "=r"(hi) : "l"(v));
}
__device__ __forceinline__ unsigned long long fma2(unsigned long long a,
                                                   unsigned long long b,
                                                   unsigned long long c) {
    unsigned long long d;
    asm("fma.rn.f32x2 %0, %1, %2, %3;" : "=l"(d) : "l"(a), "l"(b), "l"(c));
    return d;
}

__global__ void __launch_bounds__(NTHREADS) vq_fused_kernel(
    const float* __restrict__ fb,
    const float* __restrict__ emb,
    float* __restrict__ out,
    int n_elems, int nblocks, int out_size)
{
    // codebook interleaved by k-pair: lo lane = even k, hi lane = odd k
    __shared__ ulonglong2 s_A[KPAIRS];            // {pack(x0,x1), pack(y0,y1)}  8 KB
    __shared__ ulonglong2 s_B[KPAIRS];            // {pack(z0,z1), pack(w0,w1)}  8 KB
    __shared__ unsigned long long s_nh2[KPAIRS];  // pack(nh0, nh1)              4 KB
    __shared__ float  s_row[DDIM];                // 2 KB
    __shared__ float  s_m[GROUPS * NWARPS];       // packed chunk-partial best   4 KB
    __shared__ float  s_red[NWARPS];
    __shared__ float  s_scale[2];
    __shared__ bool   s_last;

    const int tid = threadIdx.x;
    const int row = blockIdx.x;
    const float* x = fb + (size_t)row * DDIM;

    // ---- load + interleave codebook, precompute -0.5*||e||^2 ----
    #pragma unroll
    for (int kp = tid; kp < KPAIRS; kp += NTHREADS) {
        float4 e0 = reinterpret_cast<const float4*>(emb)[2 * kp];
        float4 e1 = reinterpret_cast<const float4*>(emb)[2 * kp + 1];
        s_A[kp] = make_ulonglong2(pack2(e0.x, e1.x), pack2(e0.y, e1.y));
        s_B[kp] = make_ulonglong2(pack2(e0.z, e1.z), pack2(e0.w, e1.w));
        float nh0 = -0.5f * (e0.x*e0.x + e0.y*e0.y + e0.z*e0.z + e0.w*e0.w);
        float nh1 = -0.5f * (e1.x*e1.x + e1.y*e1.y + e1.z*e1.z + e1.w*e1.w);
        s_nh2[kp] = pack2(nh0, nh1);
    }

    // ---- load row, sum of squares ----
    float ss = 0.0f;
    #pragma unroll
    for (int j = tid; j < DDIM; j += NTHREADS) {
        float v = x[j];
        s_row[j] = v;
        ss = fmaf(v, v, ss);
    }
    #pragma unroll
    for (int o = 16; o > 0; o >>= 1)
        ss += __shfl_xor_sync(0xffffffffu, ss, o);
    if ((tid & 31) == 0) s_red[tid >> 5] = ss;
    __syncthreads();

    if (tid == 0) {
        float tot = 0.0f;
        #pragma unroll
        for (int w = 0; w < NWARPS; w++) tot += s_red[w];
        float scale = sqrtf(tot);
        // FloatBiter (faithful fp32)
        float xc = fminf(fmaxf(scale + 1.0f, 1.0f), 16.0f);
        float lg = logf(xc) / 1.3862943611198906f;
        float s = 0.0f;
        #pragma unroll
        for (int i = 0; i < 8; i++) {
            float base = (float)(1 << i);
            int bit = ((int)floorf(lg * base)) & 1;
            s += (float)bit / base;
        }
        s_scale[0] = scale;
        s_scale[1] = powf(4.0f, s) - 1.0f;
    }
    __syncthreads();

    const float scale = s_scale[0];

    // ---- argmax of m_k = fn.e_k - 0.5||e_k||^2 over codes ----
    // 32 lanes x 4 groups = 128 groups; 8 warps each scan a 64-pair chunk.
    // f32x2 computes both codes of a pair; 4 independent chains per lane (ILP).
    // Index rides in low 10 mantissa bits; running max is one FMNMX.
    const int gslot = tid & 31;
    const int kc = tid >> 5;              // warp id = chunk id (0..7)
    const int g0 = gslot * 4;             // first of 4 groups for this lane

    unsigned long long xq[4][4];          // {xr,xr} loop-invariant
    #pragma unroll
    for (int gg = 0; gg < 4; gg++)
        #pragma unroll
        for (int j = 0; j < 4; j++) {
            float xr = s_row[(g0 + gg) * 4 + j] / scale;   // IEEE div == fn
            xq[gg][j] = pack2(xr, xr);
        }

    float best[4] = {-3e38f, -3e38f, -3e38f, -3e38f};
    const int pbeg = kc * PPCHUNK;

    #pragma unroll 2
    for (int p2 = pbeg; p2 < pbeg + PPCHUNK; p2 += 2) {
        ulonglong2 nh01 = *reinterpret_cast<const ulonglong2*>(&s_nh2[p2]);  // LDS.128
        #pragma unroll
        for (int u = 0; u < 2; u++) {
            const int p = p2 + u;
            ulonglong2 a = s_A[p];     // warp-uniform -> broadcast LDS.128
            ulonglong2 b = s_B[p];
            const unsigned long long nh = u ? nh01.y : nh01.x;
            const unsigned k0 = 2 * p, k1 = k0 + 1;
            #pragma unroll
            for (int gg = 0; gg < 4; gg++) {
                unsigned long long acc = fma2(xq[gg][0], a.x, nh);
                acc = fma2(xq[gg][1], a.y, acc);
                acc = fma2(xq[gg][2], b.x, acc);
                acc = fma2(xq[gg][3], b.y, acc);
                unsigned mlo, mhi;
                unpack2(acc, mlo, mhi);            // register aliasing
                float q0 = __uint_as_float((mlo & PACKMASK) | k0);  // LOP3
                float q1 = __uint_as_float((mhi & PACKMASK) | k1);  // LOP3
                best[gg] = fmaxf(best[gg], q0);    // FMNMX
                best[gg] = fmaxf(best[gg], q1);    // FMNMX
            }
        }
    }
    #pragma unroll
    for (int gg = 0; gg < 4; gg++)
        s_m[(g0 + gg) * NWARPS + kc] = best[gg];
    __syncthreads();

    // ---- combine chunk partials: one group per thread (first 128 threads) ----
    float l = 0.0f;
    if (tid < GROUPS) {
        const int g = tid;
        float bm = s_m[g * NWARPS];
        #pragma unroll
        for (int c = 1; c < NWARPS; c++)
            bm = fmaxf(bm, s_m[g * NWARPS + c]);
        const int bx = (int)(__float_as_uint(bm) & IDXMASK);

        // reconstruct full-precision e[bx] from interleaved arrays
        const int kp = bx >> 1, par = bx & 1;
        unsigned ax0, ax1, ay0, ay1, bz0, bz1, bw0, bw1;
        ulonglong2 ia = s_A[kp];
        ulonglong2 ib = s_B[kp];
        unpack2(ia.x, ax0, ax1); unpack2(ia.y, ay0, ay1);
        unpack2(ib.x, bz0, bz1); unpack2(ib.y, bw0, bw1);
        float ex = __uint_as_float(par ? ax1 : ax0);
        float ey = __uint_as_float(par ? ay1 : ay0);
        float ez = __uint_as_float(par ? bz1 : bz0);
        float ew = __uint_as_float(par ? bw1 : bw0);

        const float sq = s_scale[1];
        reinterpret_cast<float4*>(out + (size_t)row * DDIM)[g] =
            make_float4(ex * sq, ey * sq, ez * sq, ew * sq);

        // loss: sum (fqn - fn)^2 (full-precision e, recomputed fn)
        float d0 = ex - s_row[g * 4 + 0] / scale;
        float d1 = ey - s_row[g * 4 + 1] / scale;
        float d2 = ez - s_row[g * 4 + 2] / scale;
        float d3 = ew - s_row[g * 4 + 3] / scale;
        l = d0*d0 + d1*d1 + d2*d2 + d3*d3;
    }
    // reduce l (threads >= 128 contribute 0)
    #pragma unroll
    for (int o = 16; o > 0; o >>= 1)
        l += __shfl_xor_sync(0xffffffffu, l, o);
    __syncthreads();   // s_red reuse
    if ((tid & 31) == 0) s_red[tid >> 5] = l;
    __syncthreads();

    // ---- last-block fused loss reduction (deterministic fixed order) ----
    if (tid == 0) {
        g_partials[row] = s_red[0] + s_red[1] + s_red[2] + s_red[3];
        __threadfence();
        int prev = atomicAdd(&g_count, 1);
        s_last = (prev == nblocks - 1);
    }
    __syncthreads();

    if (s_last) {
        __threadfence();
        float v = g_partials[tid] + g_partials[tid + 256];
        #pragma unroll
        for (int o = 16; o > 0; o >>= 1)
            v += __shfl_xor_sync(0xffffffffu, v, o);
        __syncthreads();
        if ((tid & 31) == 0) s_red[tid >> 5] = v;
        __syncthreads();
        if (tid == 0) {
            float tot = 0.0f;
            #pragma unroll
            for (int w = 0; w < NWARPS; w++) tot += s_red[w];
            float loss = tot / (float)n_elems;
            if (out_size >= n_elems + 1) out[n_elems] = loss;
            if (out_size >= n_elems + 2) out[n_elems + 1] = loss;
            g_count = 0;   // reset for next replay
        }
    }
}

extern "C" void kernel_launch(void* const* d_in, const int* in_sizes, int n_in,
                              void* d_out, int out_size)
{
    const float* fb  = (const float*)d_in[0];
    const float* emb = (const float*)d_in[1];
    float* out = (float*)d_out;

    int n = in_sizes[0];       // 262144
    int rows = n / DDIM;       // 512

    vq_fused_kernel<<<rows, NTHREADS>>>(fb, emb, out, n, rows, out_size);
}

// round 10
// speedup vs baseline: 1.1648x; 1.1648x over previous
#include <cuda_runtime.h>
#include <math.h>

#define DDIM 512        // feature dim per row
#define GROUPS 128      // groups per row
#define GPB 64          // groups per block (row split across 2 blocks)
#define KCODES 1024
#define NQUADS 256      // code quads
#define NTHREADS 128    // 4 warps
#define QCHUNK 64       // quads per warp chunk (4 warps x 64 quads = 1024 codes)
#define IDXMASK 0x3FFu
#define PACKMASK 0xFFFFFC00u      // 10-bit (code) pack
#define QIDXMASK 0xFFu
#define QPACKMASK 0xFFFFFF00u     // 8-bit (quad) pack

__device__ float g_partials[1024];
__device__ int   g_count = 0;

__global__ void __launch_bounds__(NTHREADS) vq_fused_kernel(
    const float* __restrict__ fb,
    const float* __restrict__ emb,
    float* __restrict__ out,
    int n_elems, int nblocks, int out_size)
{
    __shared__ float4 s_code[KCODES];     // 16 KB
    __shared__ float  s_nh[KCODES];       // -0.5*||e||^2, 4 KB
    __shared__ float  s_row[DDIM];        // 2 KB
    __shared__ float  s_m[GPB * 4];       // packed chunk-partial best (m|idx)
    __shared__ float  s_red[4];
    __shared__ float  s_scale[2];
    __shared__ bool   s_last;

    const int tid = threadIdx.x;
    const int row  = blockIdx.x >> 1;
    const int half = blockIdx.x & 1;      // which 64-group half of the row
    const float* x = fb + (size_t)row * DDIM;

    // ---- load codebook into smem, precompute -0.5*||e||^2 ----
    #pragma unroll
    for (int k = tid; k < KCODES; k += NTHREADS) {
        float4 e = reinterpret_cast<const float4*>(emb)[k];
        s_code[k] = e;
        s_nh[k] = -0.5f * (e.x*e.x + e.y*e.y + e.z*e.z + e.w*e.w);
    }

    // ---- load full row (norm needs all 512), sum of squares ----
    float ss = 0.0f;
    #pragma unroll
    for (int j = tid; j < DDIM; j += NTHREADS) {
        float v = x[j];
        s_row[j] = v;
        ss = fmaf(v, v, ss);
    }
    #pragma unroll
    for (int o = 16; o > 0; o >>= 1)
        ss += __shfl_xor_sync(0xffffffffu, ss, o);
    if ((tid & 31) == 0) s_red[tid >> 5] = ss;
    __syncthreads();

    if (tid == 0) {
        float tot = s_red[0] + s_red[1] + s_red[2] + s_red[3];
        float scale = sqrtf(tot);
        // FloatBiter (faithful fp32)
        float xc = fminf(fmaxf(scale + 1.0f, 1.0f), 16.0f);
        float lg = logf(xc) / 1.3862943611198906f;
        float s = 0.0f;
        #pragma unroll
        for (int i = 0; i < 8; i++) {
            float base = (float)(1 << i);
            int bit = ((int)floorf(lg * base)) & 1;
            s += (float)bit / base;
        }
        s_scale[0] = scale;
        s_scale[1] = powf(4.0f, s) - 1.0f;
    }
    __syncthreads();

    const float scale = s_scale[0];

    // ---- argmax of m_k = fn.e_k - 0.5||e_k||^2 over codes ----
    // 32 lanes x 2 groups = 64 groups; 4 warps each scan a 64-quad chunk.
    // Quad tournament: 3 FMNMX max-tree over 4 codes, pack 8-bit quad id into
    // low mantissa, one FMNMX vs running best. Winning quad rescanned once.
    const int gslot = tid & 31;
    const int kc = tid >> 5;
    const int gl0 = gslot * 2;            // local group (0..63)
    const int gg0 = half * GPB + gl0;     // global group in row

    float xr[2][4];
    #pragma unroll
    for (int gg = 0; gg < 2; gg++)
        #pragma unroll
        for (int j = 0; j < 4; j++)
            xr[gg][j] = s_row[(gg0 + gg) * 4 + j] / scale;   // IEEE div == fn

    float best[2] = {-3e38f, -3e38f};
    const int qbeg = kc * QCHUNK;

    #pragma unroll 2
    for (int q = qbeg; q < qbeg + QCHUNK; q++) {
        float4 nh4 = *reinterpret_cast<const float4*>(&s_nh[4 * q]);  // LDS.128
        float4 c0 = s_code[4 * q + 0];    // warp-uniform -> broadcast LDS.128
        float4 c1 = s_code[4 * q + 1];
        float4 c2 = s_code[4 * q + 2];
        float4 c3 = s_code[4 * q + 3];
        #pragma unroll
        for (int gg = 0; gg < 2; gg++) {
            float m0 = fmaf(xr[gg][3], c0.w, fmaf(xr[gg][2], c0.z,
                       fmaf(xr[gg][1], c0.y, fmaf(xr[gg][0], c0.x, nh4.x))));
            float m1 = fmaf(xr[gg][3], c1.w, fmaf(xr[gg][2], c1.z,
                       fmaf(xr[gg][1], c1.y, fmaf(xr[gg][0], c1.x, nh4.y))));
            float m2 = fmaf(xr[gg][3], c2.w, fmaf(xr[gg][2], c2.z,
                       fmaf(xr[gg][1], c2.y, fmaf(xr[gg][0], c2.x, nh4.z))));
            float m3 = fmaf(xr[gg][3], c3.w, fmaf(xr[gg][2], c3.z,
                       fmaf(xr[gg][1], c3.y, fmaf(xr[gg][0], c3.x, nh4.w))));
            float t = fmaxf(fmaxf(m0, m1), fmaxf(m2, m3));   // 2-level tree
            float pk = __uint_as_float((__float_as_uint(t) & QPACKMASK) | (unsigned)q);
            best[gg] = fmaxf(best[gg], pk);
        }
    }

    // ---- fix-up: rescan winning quad at 10-bit code precision ----
    #pragma unroll
    for (int gg = 0; gg < 2; gg++) {
        const int bq = (int)(__float_as_uint(best[gg]) & QIDXMASK);
        float4 nh4 = *reinterpret_cast<const float4*>(&s_nh[4 * bq]);
        const float nh[4] = {nh4.x, nh4.y, nh4.z, nh4.w};
        float fix = -3e38f;
        #pragma unroll
        for (int u = 0; u < 4; u++) {
            const int k = 4 * bq + u;
            float4 c = s_code[k];
            float m = fmaf(xr[gg][3], c.w, fmaf(xr[gg][2], c.z,
                      fmaf(xr[gg][1], c.y, fmaf(xr[gg][0], c.x, nh[u]))));
            float pk = __uint_as_float((__float_as_uint(m) & PACKMASK) | (unsigned)k);
            fix = fmaxf(fix, pk);
        }
        s_m[(gl0 + gg) * 4 + kc] = fix;
    }
    __syncthreads();

    // ---- combine chunk partials: one group per thread (first 64 threads) ----
    float l = 0.0f;
    if (tid < GPB) {
        const int gl = tid;
        const int g = half * GPB + gl;
        float bm = fmaxf(fmaxf(s_m[gl * 4 + 0], s_m[gl * 4 + 1]),
                         fmaxf(s_m[gl * 4 + 2], s_m[gl * 4 + 3]));
        const int bx = (int)(__float_as_uint(bm) & IDXMASK);

        float4 e = s_code[bx];
        const float sq = s_scale[1];
        reinterpret_cast<float4*>(out + (size_t)row * DDIM)[g] =
            make_float4(e.x * sq, e.y * sq, e.z * sq, e.w * sq);

        // loss: sum (fqn - fn)^2 (full-precision e, recomputed fn)
        float d0 = e.x - s_row[g * 4 + 0] / scale;
        float d1 = e.y - s_row[g * 4 + 1] / scale;
        float d2 = e.z - s_row[g * 4 + 2] / scale;
        float d3 = e.w - s_row[g * 4 + 3] / scale;
        l = d0*d0 + d1*d1 + d2*d2 + d3*d3;
    }
    // reduce l over first 2 warps (threads >= 64 contribute 0)
    #pragma unroll
    for (int o = 16; o > 0; o >>= 1)
        l += __shfl_xor_sync(0xffffffffu, l, o);
    __syncthreads();   // s_red reuse
    if ((tid & 31) == 0) s_red[tid >> 5] = l;
    __syncthreads();

    // ---- last-block fused loss reduction (deterministic fixed order) ----
    if (tid == 0) {
        g_partials[blockIdx.x] = s_red[0] + s_red[1];
        __threadfence();
        int prev = atomicAdd(&g_count, 1);
        s_last = (prev == nblocks - 1);
    }
    __syncthreads();

    if (s_last) {
        __threadfence();
        float v = 0.0f;
        #pragma unroll
        for (int i = 0; i < 8; i++)
            v += g_partials[tid + 128 * i];
        #pragma unroll
        for (int o = 16; o > 0; o >>= 1)
            v += __shfl_xor_sync(0xffffffffu, v, o);
        __syncthreads();
        if ((tid & 31) == 0) s_red[tid >> 5] = v;
        __syncthreads();
        if (tid == 0) {
            float loss = (s_red[0] + s_red[1] + s_red[2] + s_red[3]) / (float)n_elems;
            if (out_size >= n_elems + 1) out[n_elems] = loss;
            if (out_size >= n_elems + 2) out[n_elems + 1] = loss;
            g_count = 0;   // reset for next replay
        }
    }
}

extern "C" void kernel_launch(void* const* d_in, const int* in_sizes, int n_in,
                              void* d_out, int out_size)
{
    const float* fb  = (const float*)d_in[0];
    const float* emb = (const float*)d_in[1];
    float* out = (float*)d_out;

    int n = in_sizes[0];       // 262144
    int rows = n / DDIM;       // 512
    int nblocks = rows * 2;    // 1024 (two group-halves per row)

    vq_fused_kernel<<<nblocks, NTHREADS>>>(fb, emb, out, n, nblocks, out_size);
}